// round 1
// baseline (speedup 1.0000x reference)
#include <cuda_runtime.h>
#include <math.h>

#define NN 100000
#define EI 800000
#define EE 400000
#define HD 128
#define GB 256
#define ND 35

__device__ float d_h[NN * HD];
__device__ float d_vp[NN * HD];
__device__ float d_vl[NN * HD];
__device__ float d_aggi[NN * HD];
__device__ float d_agge[NN * HD];
__device__ float d_wint[EE];
__device__ float d_cnti[NN];
__device__ float d_cnte[NN];
__device__ float d_invi[NN];
__device__ float d_loge[NN];
__device__ float d_pool[GB * HD];
__device__ float d_fcbuf[GB * HD];

__device__ __forceinline__ float siluf(float v) {
    return v / (1.0f + expf(-v));
}

__device__ __forceinline__ void red_add_v4(float* p, float4 v) {
    asm volatile("red.global.add.v4.f32 [%0], {%1,%2,%3,%4};"
                 :: "l"(p), "f"(v.x), "f"(v.y), "f"(v.z), "f"(v.w) : "memory");
}

__global__ void k_zero_pre() {
    int i = blockIdx.x * blockDim.x + threadIdx.x;
    if (i < NN) { d_cnti[i] = 0.0f; d_cnte[i] = 0.0f; }
    if (i < GB * HD) d_pool[i] = 0.0f;
}

__global__ __launch_bounds__(128) void k_linnode(const float* __restrict__ x,
                                                 const float* __restrict__ W,
                                                 const float* __restrict__ b) {
    __shared__ float Ws[ND * HD];
    __shared__ float xs[8][ND];
    int t = threadIdx.x;
    for (int i = t; i < ND * HD; i += 128) Ws[i] = W[i];
    int n0 = blockIdx.x * 8;
    for (int i = t; i < 8 * ND; i += 128) {
        int nn = i / ND, k = i % ND;
        xs[nn][k] = x[(n0 + nn) * ND + k];
    }
    __syncthreads();
    float bb = b[t];
    for (int nn = 0; nn < 8; nn++) {
        int n = n0 + nn;
        float acc = bb;
#pragma unroll
        for (int k = 0; k < ND; k++) acc += xs[nn][k] * Ws[k * HD + t];
        d_h[n * HD + t] = siluf(acc);
        d_vp[n * HD + t] = 0.0f;
        d_vl[n * HD + t] = 0.0f;
    }
}

__global__ void k_deg_intra(const int* __restrict__ ei) {
    int e = blockIdx.x * blockDim.x + threadIdx.x;
    if (e < EI) atomicAdd(&d_cnti[ei[EI + e]], 1.0f);
}

__global__ void k_deg_inter(const int* __restrict__ ee, const float* __restrict__ pos) {
    int e = blockIdx.x * blockDim.x + threadIdx.x;
    if (e < EE) {
        int s = ee[e], d = ee[EE + e];
        float dx = pos[s * 3 + 0] - pos[d * 3 + 0];
        float dy = pos[s * 3 + 1] - pos[d * 3 + 1];
        float dz = pos[s * 3 + 2] - pos[d * 3 + 2];
        d_wint[e] = expf(-(dx * dx + dy * dy + dz * dz));
        atomicAdd(&d_cnte[d], 1.0f);
    }
}

__global__ void k_factors() {
    int n = blockIdx.x * blockDim.x + threadIdx.x;
    if (n < NN) {
        d_invi[n] = 1.0f / (d_cnti[n] + 1.0f);
        d_loge[n] = logf(d_cnte[n] + 1.0f);
    }
}

__global__ void k_zero_agg() {
    int i = blockIdx.x * blockDim.x + threadIdx.x;
    if (i < NN * HD / 4) {
        ((float4*)d_aggi)[i] = make_float4(0.f, 0.f, 0.f, 0.f);
        ((float4*)d_agge)[i] = make_float4(0.f, 0.f, 0.f, 0.f);
    }
}

// warp per edge: agg[dst] += h[src] * w
__global__ __launch_bounds__(256) void k_scatter(const int* __restrict__ idx,
                                                 const float* __restrict__ w,
                                                 int E, int which) {
    int gid = blockIdx.x * blockDim.x + threadIdx.x;
    int e = gid >> 5;
    int lane = gid & 31;
    if (e >= E) return;
    int s = __ldg(idx + e);
    int d = __ldg(idx + E + e);
    float ww = which ? __ldg(&d_wint[e]) : __ldg(w + e);
    float4 v = ((const float4*)d_h)[s * 32 + lane];
    v.x *= ww; v.y *= ww; v.z *= ww; v.w *= ww;
    float* agg = which ? d_agge : d_aggi;
    red_add_v4(agg + d * HD + lane * 4, v);
}

// fused dual-GEMM + SiLU state update
__global__ __launch_bounds__(256) void k_update(const float* __restrict__ Wi,
                                                const float* __restrict__ bi,
                                                const float* __restrict__ We,
                                                const float* __restrict__ be) {
    __shared__ float Asi[32][33];
    __shared__ float Ase[32][33];
    __shared__ float Wsi[32][HD];
    __shared__ float Wse[32][HD];
    int t = threadIdx.x;
    int tx = t & 31, ty = t >> 5;
    int n0 = blockIdx.x * 32;
    float acci[4][4], acce[4][4];
#pragma unroll
    for (int r = 0; r < 4; r++)
#pragma unroll
        for (int c = 0; c < 4; c++) { acci[r][c] = 0.f; acce[r][c] = 0.f; }

    for (int kc = 0; kc < HD; kc += 32) {
        {
            int row = t >> 3;
            int k0 = (t & 7) << 2;
            float4 va = *(const float4*)&d_aggi[(n0 + row) * HD + kc + k0];
            Asi[row][k0] = va.x; Asi[row][k0 + 1] = va.y; Asi[row][k0 + 2] = va.z; Asi[row][k0 + 3] = va.w;
            float4 vb = *(const float4*)&d_agge[(n0 + row) * HD + kc + k0];
            Ase[row][k0] = vb.x; Ase[row][k0 + 1] = vb.y; Ase[row][k0 + 2] = vb.z; Ase[row][k0 + 3] = vb.w;
        }
#pragma unroll
        for (int i = 0; i < 4; i++) {
            int idx4 = t + i * 256;
            float4 wa = ((const float4*)(Wi + kc * HD))[idx4];
            float4 wb = ((const float4*)(We + kc * HD))[idx4];
            ((float4*)&Wsi[0][0])[idx4] = wa;
            ((float4*)&Wse[0][0])[idx4] = wb;
        }
        __syncthreads();
#pragma unroll
        for (int k = 0; k < 32; k++) {
            float ai[4], ae[4];
#pragma unroll
            for (int r = 0; r < 4; r++) { ai[r] = Asi[ty * 4 + r][k]; ae[r] = Ase[ty * 4 + r][k]; }
            float4 wi4 = *(const float4*)&Wsi[k][tx * 4];
            float4 we4 = *(const float4*)&Wse[k][tx * 4];
            float wi[4] = {wi4.x, wi4.y, wi4.z, wi4.w};
            float we[4] = {we4.x, we4.y, we4.z, we4.w};
#pragma unroll
            for (int r = 0; r < 4; r++)
#pragma unroll
                for (int c = 0; c < 4; c++) {
                    acci[r][c] += ai[r] * wi[c];
                    acce[r][c] += ae[r] * we[c];
                }
        }
        __syncthreads();
    }

    int c0 = tx * 4;
    float4 bi4 = *(const float4*)&bi[c0];
    float4 be4 = *(const float4*)&be[c0];
    float bia[4] = {bi4.x, bi4.y, bi4.z, bi4.w};
    float bea[4] = {be4.x, be4.y, be4.z, be4.w};
#pragma unroll
    for (int r = 0; r < 4; r++) {
        int n = n0 + ty * 4 + r;
        float ci = d_cnti[n], inv = d_invi[n];
        float ce = d_cnte[n], lge = d_loge[n];
        float4 vp4 = *(float4*)&d_vp[n * HD + c0];
        float4 vl4 = *(float4*)&d_vl[n * HD + c0];
        float4 h4  = *(float4*)&d_h[n * HD + c0];
        float vp[4] = {vp4.x, vp4.y, vp4.z, vp4.w};
        float vl[4] = {vl4.x, vl4.y, vl4.z, vl4.w};
        float hh[4] = {h4.x, h4.y, h4.z, h4.w};
#pragma unroll
        for (int c = 0; c < 4; c++) {
            float mi = (acci[r][c] + ci * bia[c]) * inv;
            float me = (acce[r][c] + ce * bea[c]) * lge;
            vp[c] = siluf(mi + vp[c]);
            vl[c] = siluf(me + vl[c]);
            hh[c] += vp[c] + vl[c];
        }
        *(float4*)&d_vp[n * HD + c0] = make_float4(vp[0], vp[1], vp[2], vp[3]);
        *(float4*)&d_vl[n * HD + c0] = make_float4(vl[0], vl[1], vl[2], vl[3]);
        *(float4*)&d_h[n * HD + c0]  = make_float4(hh[0], hh[1], hh[2], hh[3]);
    }
}

__global__ __launch_bounds__(256) void k_pool(const int* __restrict__ batch) {
    int gid = blockIdx.x * blockDim.x + threadIdx.x;
    int n = gid >> 5;
    int lane = gid & 31;
    if (n >= NN) return;
    int b = __ldg(batch + n);
    float4 v = ((const float4*)d_h)[n * 32 + lane];
    red_add_v4(d_pool + b * HD + lane * 4, v);
}

__global__ __launch_bounds__(128) void k_fc(const float* __restrict__ W,
                                            const float* __restrict__ b,
                                            const float* __restrict__ gam,
                                            const float* __restrict__ bet,
                                            int swap) {
    __shared__ float gr[HD];
    int bid = blockIdx.x;
    int t = threadIdx.x;
    const float* gin = swap ? d_fcbuf : d_pool;
    float* gout = swap ? d_pool : d_fcbuf;
    gr[t] = gin[bid * HD + t];
    __syncthreads();
    float acc = b[t];
#pragma unroll 8
    for (int k = 0; k < HD; k++) acc += gr[k] * W[k * HD + t];
    acc = acc > 0.f ? acc : 0.01f * acc;
    float bnscale = rsqrtf(1.0f + 1e-5f);
    acc = acc * bnscale * gam[t] + bet[t];
    gout[bid * HD + t] = acc;
}

__global__ __launch_bounds__(128) void k_out(const float* __restrict__ oW,
                                             const float* __restrict__ ob,
                                             float* __restrict__ out) {
    __shared__ float part[4];
    int b = blockIdx.x;
    int t = threadIdx.x;
    float p = d_fcbuf[b * HD + t] * oW[t];
#pragma unroll
    for (int o = 16; o > 0; o >>= 1) p += __shfl_down_sync(0xffffffffu, p, o);
    if ((t & 31) == 0) part[t >> 5] = p;
    __syncthreads();
    if (t == 0) out[b] = part[0] + part[1] + part[2] + part[3] + ob[0];
}

extern "C" void kernel_launch(void* const* d_in, const int* in_sizes, int n_in,
                              void* d_out, int out_size) {
    const float* x     = (const float*)d_in[0];
    const int*   ei    = (const int*)d_in[1];
    const int*   ee    = (const int*)d_in[2];
    const float* pos   = (const float*)d_in[3];
    const float* eattr = (const float*)d_in[4];
    const int*   batch = (const int*)d_in[5];
    const float* lnW   = (const float*)d_in[6];
    const float* lnb   = (const float*)d_in[7];
    const float* Wi    = (const float*)d_in[8];
    const float* bi    = (const float*)d_in[9];
    const float* We    = (const float*)d_in[10];
    const float* be    = (const float*)d_in[11];
    const float* fcW   = (const float*)d_in[12];
    const float* fcb   = (const float*)d_in[13];
    const float* gam   = (const float*)d_in[14];
    const float* bet   = (const float*)d_in[15];
    const float* oW    = (const float*)d_in[16];
    const float* ob    = (const float*)d_in[17];
    float* out = (float*)d_out;

    k_zero_pre<<<(NN + 255) / 256, 256>>>();
    k_linnode<<<NN / 8, 128>>>(x, lnW, lnb);
    k_deg_intra<<<(EI + 255) / 256, 256>>>(ei);
    k_deg_inter<<<(EE + 255) / 256, 256>>>(ee, pos);
    k_factors<<<(NN + 255) / 256, 256>>>();

    for (int l = 0; l < 4; l++) {
        k_zero_agg<<<(NN * HD / 4 + 255) / 256, 256>>>();
        k_scatter<<<(EI * 32 + 255) / 256, 256>>>(ei, eattr, EI, 0);
        k_scatter<<<(EE * 32 + 255) / 256, 256>>>(ee, eattr, EE, 1);
        k_update<<<NN / 32, 256>>>(Wi + l * HD * HD, bi + l * HD,
                                   We + l * HD * HD, be + l * HD);
    }

    k_pool<<<(NN * 32 + 255) / 256, 256>>>(batch);
    k_fc<<<GB, 128>>>(fcW + 0 * HD * HD, fcb + 0 * HD, gam + 0 * HD, bet + 0 * HD, 0);
    k_fc<<<GB, 128>>>(fcW + 1 * HD * HD, fcb + 1 * HD, gam + 1 * HD, bet + 1 * HD, 1);
    k_fc<<<GB, 128>>>(fcW + 2 * HD * HD, fcb + 2 * HD, gam + 2 * HD, bet + 2 * HD, 0);
    k_out<<<GB, 128>>>(oW, ob, out);
}